// round 16
// baseline (speedup 1.0000x reference)
#include <cuda_runtime.h>
#include <cuda_bf16.h>
#include <stdint.h>

#define BB 16
#define CC 512
#define NN 4096
#define CI_ 64
#define CH_ 256
#define PP 1024

// ---------------- device scratch (no dynamic alloc allowed) ----------------
__device__ __nv_bfloat16 d_xt[(size_t)BB * NN * CC];   // [B][N][C]
__device__ __nv_bfloat16 d_wf[CI_ * CC];               // pre-scaled by log2(e)
__device__ __nv_bfloat16 d_wg[CI_ * CC];
__device__ __nv_bfloat16 d_wh[CH_ * CC];
__device__ __nv_bfloat16 d_wv[CC * CH_];
__device__ __nv_bfloat16 d_f[(size_t)BB * NN * CI_];   // [B][N][CI]
__device__ __nv_bfloat16 d_g[(size_t)BB * PP * CI_];   // [B][P][CI]
__device__ __nv_bfloat16 d_hT[(size_t)BB * CH_ * PP];  // [B][CH][P]
__device__ __nv_bfloat16 d_v[(size_t)BB * NN * CH_];   // [B][N][CH]

// ---------------- helpers ----------------
__device__ __forceinline__ uint32_t smem_u32(const void* p) {
  return (uint32_t)__cvta_generic_to_shared(p);
}
__device__ __forceinline__ void ldsm_x4(uint32_t& r0, uint32_t& r1,
                                        uint32_t& r2, uint32_t& r3,
                                        uint32_t addr) {
  asm volatile("ldmatrix.sync.aligned.m8n8.x4.shared.b16 {%0,%1,%2,%3}, [%4];\n"
               : "=r"(r0), "=r"(r1), "=r"(r2), "=r"(r3) : "r"(addr));
}
__device__ __forceinline__ void mma16816(float* d, uint32_t a0, uint32_t a1,
                                         uint32_t a2, uint32_t a3,
                                         uint32_t b0, uint32_t b1) {
  asm volatile(
      "mma.sync.aligned.m16n8k16.row.col.f32.bf16.bf16.f32 "
      "{%0,%1,%2,%3}, {%4,%5,%6,%7}, {%8,%9}, {%0,%1,%2,%3};\n"
      : "+f"(d[0]), "+f"(d[1]), "+f"(d[2]), "+f"(d[3])
      : "r"(a0), "r"(a1), "r"(a2), "r"(a3), "r"(b0), "r"(b1));
}
__device__ __forceinline__ uint32_t bf2pack(float lo, float hi) {
  __nv_bfloat162 h = __floats2bfloat162_rn(lo, hi);
  return *(uint32_t*)&h;
}
__device__ __forceinline__ void cp16(void* dst, const void* src) {
  asm volatile("cp.async.cg.shared.global [%0], [%1], 16;\n" ::
               "r"(smem_u32(dst)), "l"(src));
}
__device__ __forceinline__ void cp_commit() {
  asm volatile("cp.async.commit_group;\n" ::: "memory");
}
template <int N>
__device__ __forceinline__ void cp_wait() {
  asm volatile("cp.async.wait_group %0;\n" :: "n"(N) : "memory");
}
#define NAMED_BAR(id, cnt) \
  asm volatile("bar.sync %0, %1;" :: "r"(id), "r"(cnt) : "memory")

// Schraudolph 2^s in the int pipe: u = 0x3f800000 + rint(s*2^23 - 360448)
__device__ __forceinline__ uint32_t exp2_bits(float s) {
  int i = __float2int_rn(fmaf(s, 8388608.f, -360448.f));
  return 0x3f800000u + (uint32_t)i;
}

// ---------------- K0: x transpose + (b==0) weight conversion -----------------
__global__ __launch_bounds__(256) void convert_x(
    const float* __restrict__ x, const float* __restrict__ Wf,
    const float* __restrict__ Wg, const float* __restrict__ Wh,
    const float* __restrict__ Wv) {
  __shared__ float s[64][68];
  const int b = blockIdx.z, c0 = blockIdx.y * 64, n0 = blockIdx.x * 64;
  const int tid = threadIdx.x;
#pragma unroll
  for (int i = 0; i < 4; i++) {
    int flat = tid + i * 256;
    int row = flat >> 4, col4 = (flat & 15) * 4;
    *(float4*)&s[row][col4] =
        *(const float4*)&x[(((size_t)b * CC) + c0 + row) * NN + n0 + col4];
  }
  __syncthreads();
#pragma unroll
  for (int i = 0; i < 2; i++) {
    int flat = tid + i * 256;
    int n = flat >> 3, seg = flat & 7;
    __nv_bfloat16 tmp[8];
#pragma unroll
    for (int c = 0; c < 8; c++)
      tmp[c] = __float2bfloat16_rn(s[seg * 8 + c][n]);
    *(uint4*)&d_xt[((size_t)b * NN + n0 + n) * CC + c0 + seg * 8] =
        *(uint4*)tmp;
  }
  // fold weight conversion into the b==0 slice of the grid (512 blocks)
  if (b == 0) {
    int gflat = (blockIdx.y * 64 + blockIdx.x) * 256 + tid;  // 0..131071
    // wf+wg: 32768 each
    if (gflat < CI_ * CC) {
      d_wf[gflat] = __float2bfloat16_rn(Wf[gflat] * 1.4426950408889634f);
      d_wg[gflat] = __float2bfloat16_rn(Wg[gflat]);
    }
    // wh, wv: 131072 each -> every thread does one of each
    d_wh[gflat] = __float2bfloat16_rn(Wh[gflat]);
    d_wv[gflat] = __float2bfloat16_rn(Wv[gflat]);
  }
}

// ---------------- K1: projections v2 (128 co x 128 n, 3 chunk-sets) ---------
#define PRJ_STAGE 18432
#define PRJ_SMEM (2 * PRJ_STAGE * 2)  // 73728 B; conv_s [128][132] fp32 aliases

__device__ __forceinline__ const __nv_bfloat16* prj_wrow(int cs, int row) {
  if (cs == 0)
    return (row < 64) ? d_wf + (size_t)row * CC : d_wg + (size_t)(row - 64) * CC;
  return d_wh + (size_t)((cs - 1) * 128 + row) * CC;
}

__global__ void __launch_bounds__(256, 2) proj_mma() {
  extern __shared__ __align__(16) char smc[];
  const int b = blockIdx.z, cs = blockIdx.y, n0 = blockIdx.x * 128;
  const int tid = threadIdx.x, lane = tid & 31, wid = tid >> 5;
  const int warp_m = wid >> 1;  // 0..3 : 32 co rows
  const int warp_n = wid & 1;   // 0..1 : 64 n cols

  float acc[2][8][4];
#pragma unroll
  for (int m = 0; m < 2; m++)
#pragma unroll
    for (int i = 0; i < 8; i++)
#pragma unroll
      for (int j = 0; j < 4; j++) acc[m][i][j] = 0.f;

  const int a_r15 = lane & 15;
  const int a_col = (lane >> 4) << 3;
  const int g8 = lane >> 3, r8 = lane & 7;
  const int b_row = ((g8 >> 1) << 3) + r8;
  const int b_colk = (g8 & 1) << 3;

  const __nv_bfloat16* xtb = d_xt + ((size_t)b * NN + n0) * CC;

  {
    __nv_bfloat16* ws = (__nv_bfloat16*)smc;
    __nv_bfloat16* xs = ws + 128 * 72;
#pragma unroll
    for (int i = 0; i < 4; i++) {
      int flat = tid + i * 256;
      int row = flat >> 3, seg = flat & 7;
      cp16(&ws[row * 72 + seg * 8], prj_wrow(cs, row) + seg * 8);
      cp16(&xs[row * 72 + seg * 8], &xtb[(size_t)row * CC + seg * 8]);
    }
    cp_commit();
  }

  for (int c = 0; c < 8; c++) {
    cp_wait<0>();
    __syncthreads();
    if (c < 7) {
      int kc = (c + 1) * 64;
      __nv_bfloat16* ws = (__nv_bfloat16*)smc + ((c + 1) & 1) * PRJ_STAGE;
      __nv_bfloat16* xs = ws + 128 * 72;
#pragma unroll
      for (int i = 0; i < 4; i++) {
        int flat = tid + i * 256;
        int row = flat >> 3, seg = flat & 7;
        cp16(&ws[row * 72 + seg * 8], prj_wrow(cs, row) + kc + seg * 8);
        cp16(&xs[row * 72 + seg * 8], &xtb[(size_t)row * CC + kc + seg * 8]);
      }
      cp_commit();
    }
    __nv_bfloat16* ws = (__nv_bfloat16*)smc + (c & 1) * PRJ_STAGE;
    __nv_bfloat16* xs = ws + 128 * 72;
#pragma unroll
    for (int ks = 0; ks < 64; ks += 16) {
      uint32_t a[2][4];
#pragma unroll
      for (int mf = 0; mf < 2; mf++)
        ldsm_x4(a[mf][0], a[mf][1], a[mf][2], a[mf][3],
                smem_u32(&ws[(warp_m * 32 + mf * 16 + a_r15) * 72 + ks + a_col]));
#pragma unroll
      for (int nf2 = 0; nf2 < 4; nf2++) {
        uint32_t b0r, b1r, b2r, b3r;
        ldsm_x4(b0r, b1r, b2r, b3r,
                smem_u32(&xs[(warp_n * 64 + nf2 * 16 + b_row) * 72 + ks + b_colk]));
#pragma unroll
        for (int mf = 0; mf < 2; mf++) {
          mma16816(acc[mf][nf2 * 2], a[mf][0], a[mf][1], a[mf][2], a[mf][3],
                   b0r, b1r);
          mma16816(acc[mf][nf2 * 2 + 1], a[mf][0], a[mf][1], a[mf][2],
                   a[mf][3], b2r, b3r);
        }
      }
    }
  }
  __syncthreads();  // conv_s aliases stage buffers

  float* conv_s = (float*)smc;  // [128][132]
#pragma unroll
  for (int mf = 0; mf < 2; mf++) {
    int row0 = warp_m * 32 + mf * 16 + (lane >> 2);
#pragma unroll
    for (int nf = 0; nf < 8; nf++) {
      int col = warp_n * 64 + nf * 8 + (lane & 3) * 2;
      *(float2*)&conv_s[row0 * 132 + col] =
          make_float2(acc[mf][nf][0], acc[mf][nf][1]);
      *(float2*)&conv_s[(row0 + 8) * 132 + col] =
          make_float2(acc[mf][nf][2], acc[mf][nf][3]);
    }
  }
  __syncthreads();

  if (cs == 0) {
#pragma unroll
    for (int i = 0; i < 4; i++) {
      int flat = tid + i * 256;
      int n = flat >> 3, cseg = flat & 7;
      __nv_bfloat16 tmp[8];
#pragma unroll
      for (int c = 0; c < 8; c++)
        tmp[c] = __float2bfloat16_rn(conv_s[(cseg * 8 + c) * 132 + n]);
      *(uint4*)&d_f[((size_t)b * NN + n0 + n) * CI_ + cseg * 8] = *(uint4*)tmp;
    }
    {
      int pj = tid >> 3, cseg = tid & 7;
      __nv_bfloat16 tmp[8];
#pragma unroll
      for (int c = 0; c < 8; c++) {
        const float* r0 = &conv_s[(64 + cseg * 8 + c) * 132];
        float m = fmaxf(fmaxf(r0[2 * pj], r0[2 * pj + 1]),
                        fmaxf(r0[64 + 2 * pj], r0[65 + 2 * pj]));
        tmp[c] = __float2bfloat16_rn(m);
      }
      *(uint4*)&d_g[((size_t)b * PP + blockIdx.x * 32 + pj) * CI_ + cseg * 8] =
          *(uint4*)tmp;
    }
  } else {
#pragma unroll
    for (int i = 0; i < 2; i++) {
      int flat = tid + i * 256;
      int ch = flat >> 2, pseg = flat & 3;
      const float* r0 = &conv_s[ch * 132];
      __nv_bfloat16 tmp[8];
#pragma unroll
      for (int j = 0; j < 8; j++) {
        int pj = pseg * 8 + j;
        float m = fmaxf(fmaxf(r0[2 * pj], r0[2 * pj + 1]),
                        fmaxf(r0[64 + 2 * pj], r0[65 + 2 * pj]));
        tmp[j] = __float2bfloat16_rn(m);
      }
      *(uint4*)&d_hT[((size_t)b * CH_ + (cs - 1) * 128 + ch) * PP +
                     blockIdx.x * 32 + pseg * 8] = *(uint4*)tmp;
    }
  }
}

// ---------------- K2: attention (bf16 MMA; prefetch hoisted to chunk top) ---
#define AT_FS 0
#define AT_GS 4608
#define AT_HS 13824
#define AT_PS 50688
#define AT_END 55296
#define ATTN_SMEM (AT_END * 2 + 64 * 4)  // 110848 B -> 2 CTAs/SM

__global__ void __launch_bounds__(256, 2) attn_mma() {
  extern __shared__ __align__(16) char smc[];
  __nv_bfloat16* fs = (__nv_bfloat16*)smc + AT_FS;
  __nv_bfloat16* ps = (__nv_bfloat16*)smc + AT_PS;
  float* rowsum = (float*)(smc + AT_END * 2);

  const int b = blockIdx.y, n0 = blockIdx.x * 64;
  const int tid = threadIdx.x, lane = tid & 31, wid = tid >> 5;
  const int wm = wid >> 2;  // 0..1 : 32 query rows
  const int wn = wid & 3;   // 0..3 : 16 p (scores) / 64 ch (value)

  if (tid < 64) rowsum[tid] = 0.f;

  const __nv_bfloat16* fb = d_f + ((size_t)b * NN + n0) * CI_;
  const __nv_bfloat16* gb = d_g + (size_t)b * PP * CI_;
  const __nv_bfloat16* hb = d_hT + (size_t)b * CH_ * PP;
  const int ld_row = tid >> 3, ld_seg = tid & 7;

  {
#pragma unroll
    for (int i = 0; i < 2; i++) {
      int row = ld_row + i * 32;
      cp16(&fs[row * 72 + ld_seg * 8], &fb[(size_t)row * CI_ + ld_seg * 8]);
    }
    __nv_bfloat16* gs = (__nv_bfloat16*)smc + AT_GS;
    __nv_bfloat16* hs = (__nv_bfloat16*)smc + AT_HS;
#pragma unroll
    for (int i = 0; i < 2; i++) {
      int row = ld_row + i * 32;
      cp16(&gs[row * 72 + ld_seg * 8], &gb[(size_t)row * CI_ + ld_seg * 8]);
    }
#pragma unroll
    for (int i = 0; i < 8; i++) {
      int row = ld_row + i * 32;
      cp16(&hs[row * 72 + ld_seg * 8], &hb[(size_t)row * PP + ld_seg * 8]);
    }
    cp_commit();
  }

  const int a_col = (lane >> 4) << 3;
  const int a_r15 = lane & 15;
  const int g8 = lane >> 3, r8 = lane & 7;
  const int b_row = ((g8 >> 1) << 3) + r8;
  const int b_colk = (g8 & 1) << 3;

  float vacc[2][8][4];
#pragma unroll
  for (int m = 0; m < 2; m++)
#pragma unroll
    for (int c = 0; c < 8; c++)
#pragma unroll
      for (int j = 0; j < 4; j++) vacc[m][c][j] = 0.f;
  float rs[2][2] = {{0.f, 0.f}, {0.f, 0.f}};

  for (int c = 0; c < 16; c++) {
    cp_wait<0>();
    __syncthreads();  // chunk c ready; all warps past value(c-1)

    // prefetch c+1 at chunk top: buffer (c+1)&1 is dead (last read by
    // value(c-1), which every warp completed before the barrier above).
    if (c < 15) {
      int pc = (c + 1) * 64;
      __nv_bfloat16* gs2 = (__nv_bfloat16*)smc + AT_GS + ((c + 1) & 1) * 4608;
      __nv_bfloat16* hs2 = (__nv_bfloat16*)smc + AT_HS + ((c + 1) & 1) * 18432;
#pragma unroll
      for (int i = 0; i < 2; i++) {
        int row = ld_row + i * 32;
        cp16(&gs2[row * 72 + ld_seg * 8],
             &gb[(size_t)(pc + row) * CI_ + ld_seg * 8]);
      }
#pragma unroll
      for (int i = 0; i < 8; i++) {
        int row = ld_row + i * 32;
        cp16(&hs2[row * 72 + ld_seg * 8],
             &hb[(size_t)row * PP + pc + ld_seg * 8]);
      }
      cp_commit();
    }

    __nv_bfloat16* gs = (__nv_bfloat16*)smc + AT_GS + (c & 1) * 4608;
    __nv_bfloat16* hs = (__nv_bfloat16*)smc + AT_HS + (c & 1) * 18432;

    // ---- scores: [64 n][64 p], K=64 (log2-domain) ----
    float sacc[2][2][4];
#pragma unroll
    for (int m = 0; m < 2; m++)
#pragma unroll
      for (int p = 0; p < 2; p++)
#pragma unroll
        for (int j = 0; j < 4; j++) sacc[m][p][j] = 0.f;
#pragma unroll
    for (int ks = 0; ks < 64; ks += 16) {
      uint32_t a[2][4];
#pragma unroll
      for (int mf = 0; mf < 2; mf++)
        ldsm_x4(a[mf][0], a[mf][1], a[mf][2], a[mf][3],
                smem_u32(&fs[(wm * 32 + mf * 16 + a_r15) * 72 + ks + a_col]));
      uint32_t b0r, b1r, b2r, b3r;
      ldsm_x4(b0r, b1r, b2r, b3r,
              smem_u32(&gs[(wn * 16 + b_row) * 72 + ks + b_colk]));
#pragma unroll
      for (int mf = 0; mf < 2; mf++) {
        mma16816(sacc[mf][0], a[mf][0], a[mf][1], a[mf][2], a[mf][3], b0r, b1r);
        mma16816(sacc[mf][1], a[mf][0], a[mf][1], a[mf][2], a[mf][3], b2r, b3r);
      }
    }
    // Schraudolph 2^s, probs -> smem via PRMT
#pragma unroll
    for (int mf = 0; mf < 2; mf++) {
      int row = wm * 32 + mf * 16 + (lane >> 2);
#pragma unroll
      for (int pf = 0; pf < 2; pf++) {
        uint32_t u0 = exp2_bits(sacc[mf][pf][0]);
        uint32_t u1 = exp2_bits(sacc[mf][pf][1]);
        uint32_t u2 = exp2_bits(sacc[mf][pf][2]);
        uint32_t u3 = exp2_bits(sacc[mf][pf][3]);
        rs[mf][0] += __uint_as_float(u0) + __uint_as_float(u1);
        rs[mf][1] += __uint_as_float(u2) + __uint_as_float(u3);
        int col = wn * 16 + pf * 8 + (lane & 3) * 2;
        *(uint32_t*)&ps[row * 72 + col] = __byte_perm(u0, u1, 0x7632);
        *(uint32_t*)&ps[(row + 8) * 72 + col] = __byte_perm(u2, u3, 0x7632);
      }
    }
    NAMED_BAR(1 + wm, 128);  // ps rows [wm*32,+32) complete within wm-group

    // ---- value: [64 n][256 ch], K=64 ----
#pragma unroll
    for (int ks = 0; ks < 64; ks += 16) {
      uint32_t a[2][4];
#pragma unroll
      for (int mf = 0; mf < 2; mf++)
        ldsm_x4(a[mf][0], a[mf][1], a[mf][2], a[mf][3],
                smem_u32(&ps[(wm * 32 + mf * 16 + a_r15) * 72 + ks + a_col]));
#pragma unroll
      for (int cf2 = 0; cf2 < 4; cf2++) {
        int cb = wn * 64 + cf2 * 16;
        uint32_t b0r, b1r, b2r, b3r;
        ldsm_x4(b0r, b1r, b2r, b3r,
                smem_u32(&hs[(cb + b_row) * 72 + ks + b_colk]));
#pragma unroll
        for (int mf = 0; mf < 2; mf++) {
          mma16816(vacc[mf][cf2 * 2], a[mf][0], a[mf][1], a[mf][2], a[mf][3],
                   b0r, b1r);
          mma16816(vacc[mf][cf2 * 2 + 1], a[mf][0], a[mf][1], a[mf][2],
                   a[mf][3], b2r, b3r);
        }
      }
    }
  }

  // rowsum: one reduce + atomic at the end
#pragma unroll
  for (int mf = 0; mf < 2; mf++)
#pragma unroll
    for (int h = 0; h < 2; h++) {
      float v = rs[mf][h];
      v += __shfl_xor_sync(0xffffffffu, v, 1);
      v += __shfl_xor_sync(0xffffffffu, v, 2);
      if ((lane & 3) == 0)
        atomicAdd(&rowsum[wm * 32 + mf * 16 + (lane >> 2) + h * 8], v);
    }
  __syncthreads();

  // normalize + write v [B][N][CH] bf16
#pragma unroll
  for (int mf = 0; mf < 2; mf++) {
    int r = wm * 32 + mf * 16 + (lane >> 2);
    float inv0 = 1.f / rowsum[r];
    float inv8 = 1.f / rowsum[r + 8];
    size_t base0 = ((size_t)b * NN + n0 + r) * CH_;
    size_t base8 = ((size_t)b * NN + n0 + r + 8) * CH_;
#pragma unroll
    for (int cf = 0; cf < 8; cf++) {
      int ch = wn * 64 + cf * 8 + (lane & 3) * 2;
      *(uint32_t*)&d_v[base0 + ch] =
          bf2pack(vacc[mf][cf][0] * inv0, vacc[mf][cf][1] * inv0);
      *(uint32_t*)&d_v[base8 + ch] =
          bf2pack(vacc[mf][cf][2] * inv8, vacc[mf][cf][3] * inv8);
    }
  }
}

// ---------------- K3: out = x + beta*(Wv@v), N-tile 256, cp.async ----------
#define OUT_STAGE 23040
#define OUT_SMEM (2 * OUT_STAGE * 2)

__global__ void __launch_bounds__(256, 2) outconv_mma(
    const float* __restrict__ x, const float* __restrict__ beta,
    float* __restrict__ out) {
  extern __shared__ __align__(16) char smc[];
  const int b = blockIdx.z, co0 = blockIdx.y * 64, n0 = blockIdx.x * 256;
  const int tid = threadIdx.x, lane = tid & 31, wid = tid >> 5;
  const int warp_m = wid >> 2;
  const int warp_n = wid & 3;

  float acc[2][8][4];
#pragma unroll
  for (int m = 0; m < 2; m++)
#pragma unroll
    for (int i = 0; i < 8; i++)
#pragma unroll
      for (int j = 0; j < 4; j++) acc[m][i][j] = 0.f;

  const int a_r15 = lane & 15;
  const int a_col = (lane >> 4) << 3;
  const int g8 = lane >> 3, r8 = lane & 7;
  const int b_row = ((g8 >> 1) << 3) + r8;
  const int b_colk = (g8 & 1) << 3;

  const __nv_bfloat16* vb = d_v + ((size_t)b * NN + n0) * CH_;
  const __nv_bfloat16* Wb = d_wv + (size_t)co0 * CH_;
  const int ld_row = tid >> 3, ld_seg = tid & 7;

  {
    __nv_bfloat16* ws = (__nv_bfloat16*)smc;
    __nv_bfloat16* vs = ws + 4608;
#pragma unroll
    for (int i = 0; i < 2; i++) {
      int row = ld_row + i * 32;
      cp16(&ws[row * 72 + ld_seg * 8], &Wb[(size_t)row * CH_ + ld_seg * 8]);
    }
#pragma unroll
    for (int i = 0; i < 8; i++) {
      int row = ld_row + i * 32;
      cp16(&vs[row * 72 + ld_seg * 8], &vb[(size_t)row * CH_ + ld_seg * 8]);
    }
    cp_commit();
  }

  for (int c = 0; c < 4; c++) {
    cp_wait<0>();
    __syncthreads();
    if (c < 3) {
      int kc = (c + 1) * 64;
      __nv_bfloat16* ws = (__nv_bfloat16*)smc + ((c + 1) & 1) * OUT_STAGE;
      __nv_bfloat16* vs = ws + 4608;
#pragma unroll
      for (int i = 0; i < 2; i++) {
        int row = ld_row + i * 32;
        cp16(&ws[row * 72 + ld_seg * 8],
             &Wb[(size_t)row * CH_ + kc + ld_seg * 8]);
      }
#pragma unroll
      for (int i = 0; i < 8; i++) {
        int row = ld_row + i * 32;
        cp16(&vs[row * 72 + ld_seg * 8],
             &vb[(size_t)row * CH_ + kc + ld_seg * 8]);
      }
      cp_commit();
    }
    __nv_bfloat16* ws = (__nv_bfloat16*)smc + (c & 1) * OUT_STAGE;
    __nv_bfloat16* vs = ws + 4608;
#pragma unroll
    for (int ks = 0; ks < 64; ks += 16) {
      uint32_t a[2][4];
#pragma unroll
      for (int mf = 0; mf < 2; mf++)
        ldsm_x4(a[mf][0], a[mf][1], a[mf][2], a[mf][3],
                smem_u32(&ws[(warp_m * 32 + mf * 16 + a_r15) * 72 + ks + a_col]));
#pragma unroll
      for (int nf2 = 0; nf2 < 4; nf2++) {
        uint32_t b0r, b1r, b2r, b3r;
        ldsm_x4(b0r, b1r, b2r, b3r,
                smem_u32(&vs[(warp_n * 64 + nf2 * 16 + b_row) * 72 + ks + b_colk]));
#pragma unroll
        for (int mf = 0; mf < 2; mf++) {
          mma16816(acc[mf][nf2 * 2], a[mf][0], a[mf][1], a[mf][2], a[mf][3],
                   b0r, b1r);
          mma16816(acc[mf][nf2 * 2 + 1], a[mf][0], a[mf][1], a[mf][2],
                   a[mf][3], b2r, b3r);
        }
      }
    }
  }

  const float bv = beta[0];
#pragma unroll
  for (int mf = 0; mf < 2; mf++) {
    int row = warp_m * 32 + mf * 16 + (lane >> 2);
#pragma unroll
    for (int nf = 0; nf < 8; nf++) {
      int col = warp_n * 64 + nf * 8 + (lane & 3) * 2;
      size_t idx0 = ((size_t)b * CC + co0 + row) * NN + n0 + col;
      size_t idx8 = ((size_t)b * CC + co0 + row + 8) * NN + n0 + col;
      float2 xv0 = *(const float2*)&x[idx0];
      float2 xv8 = *(const float2*)&x[idx8];
      *(float2*)&out[idx0] =
          make_float2(xv0.x + bv * acc[mf][nf][0], xv0.y + bv * acc[mf][nf][1]);
      *(float2*)&out[idx8] =
          make_float2(xv8.x + bv * acc[mf][nf][2], xv8.y + bv * acc[mf][nf][3]);
    }
  }
}

// ---------------------------------------------------------------------------
extern "C" void kernel_launch(void* const* d_in, const int* in_sizes, int n_in,
                              void* d_out, int out_size) {
  (void)in_sizes; (void)n_in; (void)out_size;
  const float* x = (const float*)d_in[0];
  const float* Wf = (const float*)d_in[1];
  const float* Wg = (const float*)d_in[2];
  const float* Wh = (const float*)d_in[3];
  const float* Wv = (const float*)d_in[4];
  const float* beta = (const float*)d_in[5];
  float* out = (float*)d_out;

  convert_x<<<dim3(64, 8, BB), 256>>>(x, Wf, Wg, Wh, Wv);

  cudaFuncSetAttribute(proj_mma, cudaFuncAttributeMaxDynamicSharedMemorySize,
                       PRJ_SMEM);
  proj_mma<<<dim3(32, 3, BB), 256, PRJ_SMEM>>>();

  cudaFuncSetAttribute(attn_mma, cudaFuncAttributeMaxDynamicSharedMemorySize,
                       ATTN_SMEM);
  attn_mma<<<dim3(64, BB), 256, ATTN_SMEM>>>();

  cudaFuncSetAttribute(outconv_mma, cudaFuncAttributeMaxDynamicSharedMemorySize,
                       OUT_SMEM);
  outconv_mma<<<dim3(16, 8, BB), 256, OUT_SMEM>>>(x, beta, out);
}

// round 17
// speedup vs baseline: 1.0116x; 1.0116x over previous
#include <cuda_runtime.h>
#include <cuda_bf16.h>
#include <stdint.h>

#define BB 16
#define CC 512
#define NN 4096
#define CI_ 64
#define CH_ 256
#define PP 1024

// ---------------- device scratch (no dynamic alloc allowed) ----------------
__device__ __nv_bfloat16 d_xt[(size_t)BB * NN * CC];   // [B][N][C]
__device__ __nv_bfloat16 d_wf[CI_ * CC];               // pre-scaled by log2(e)
__device__ __nv_bfloat16 d_wg[CI_ * CC];
__device__ __nv_bfloat16 d_wh[CH_ * CC];
__device__ __nv_bfloat16 d_wv[CC * CH_];
__device__ __nv_bfloat16 d_f[(size_t)BB * NN * CI_];   // [B][N][CI]
__device__ __nv_bfloat16 d_g[(size_t)BB * PP * CI_];   // [B][P][CI]
__device__ __nv_bfloat16 d_hT[(size_t)BB * CH_ * PP];  // [B][CH][P]
__device__ __nv_bfloat16 d_v[(size_t)BB * NN * CH_];   // [B][N][CH]

// ---------------- helpers ----------------
__device__ __forceinline__ uint32_t smem_u32(const void* p) {
  return (uint32_t)__cvta_generic_to_shared(p);
}
__device__ __forceinline__ void ldsm_x4(uint32_t& r0, uint32_t& r1,
                                        uint32_t& r2, uint32_t& r3,
                                        uint32_t addr) {
  asm volatile("ldmatrix.sync.aligned.m8n8.x4.shared.b16 {%0,%1,%2,%3}, [%4];\n"
               : "=r"(r0), "=r"(r1), "=r"(r2), "=r"(r3) : "r"(addr));
}
__device__ __forceinline__ void mma16816(float* d, uint32_t a0, uint32_t a1,
                                         uint32_t a2, uint32_t a3,
                                         uint32_t b0, uint32_t b1) {
  asm volatile(
      "mma.sync.aligned.m16n8k16.row.col.f32.bf16.bf16.f32 "
      "{%0,%1,%2,%3}, {%4,%5,%6,%7}, {%8,%9}, {%0,%1,%2,%3};\n"
      : "+f"(d[0]), "+f"(d[1]), "+f"(d[2]), "+f"(d[3])
      : "r"(a0), "r"(a1), "r"(a2), "r"(a3), "r"(b0), "r"(b1));
}
__device__ __forceinline__ uint32_t bf2pack(float lo, float hi) {
  __nv_bfloat162 h = __floats2bfloat162_rn(lo, hi);
  return *(uint32_t*)&h;
}
__device__ __forceinline__ void cp16(void* dst, const void* src) {
  asm volatile("cp.async.cg.shared.global [%0], [%1], 16;\n" ::
               "r"(smem_u32(dst)), "l"(src));
}
__device__ __forceinline__ void cp_commit() {
  asm volatile("cp.async.commit_group;\n" ::: "memory");
}
template <int N>
__device__ __forceinline__ void cp_wait() {
  asm volatile("cp.async.wait_group %0;\n" :: "n"(N) : "memory");
}
#define NAMED_BAR(id, cnt) \
  asm volatile("bar.sync %0, %1;" :: "r"(id), "r"(cnt) : "memory")

// Schraudolph 2^s in the int pipe: u = 0x3f800000 + rint(s*2^23 - 360448)
__device__ __forceinline__ uint32_t exp2_bits(float s) {
  int i = __float2int_rn(fmaf(s, 8388608.f, -360448.f));
  return 0x3f800000u + (uint32_t)i;
}

// ---------------- K0: x transpose + (b==0) weight conversion -----------------
__global__ __launch_bounds__(256) void convert_x(
    const float* __restrict__ x, const float* __restrict__ Wf,
    const float* __restrict__ Wg, const float* __restrict__ Wh,
    const float* __restrict__ Wv) {
  __shared__ float s[64][68];
  const int b = blockIdx.z, c0 = blockIdx.y * 64, n0 = blockIdx.x * 64;
  const int tid = threadIdx.x;
#pragma unroll
  for (int i = 0; i < 4; i++) {
    int flat = tid + i * 256;
    int row = flat >> 4, col4 = (flat & 15) * 4;
    *(float4*)&s[row][col4] =
        *(const float4*)&x[(((size_t)b * CC) + c0 + row) * NN + n0 + col4];
  }
  __syncthreads();
#pragma unroll
  for (int i = 0; i < 2; i++) {
    int flat = tid + i * 256;
    int n = flat >> 3, seg = flat & 7;
    __nv_bfloat16 tmp[8];
#pragma unroll
    for (int c = 0; c < 8; c++)
      tmp[c] = __float2bfloat16_rn(s[seg * 8 + c][n]);
    *(uint4*)&d_xt[((size_t)b * NN + n0 + n) * CC + c0 + seg * 8] =
        *(uint4*)tmp;
  }
  if (b == 0) {
    int gflat = (blockIdx.y * 64 + blockIdx.x) * 256 + tid;  // 0..131071
    if (gflat < CI_ * CC) {
      d_wf[gflat] = __float2bfloat16_rn(Wf[gflat] * 1.4426950408889634f);
      d_wg[gflat] = __float2bfloat16_rn(Wg[gflat]);
    }
    d_wh[gflat] = __float2bfloat16_rn(Wh[gflat]);
    d_wv[gflat] = __float2bfloat16_rn(Wv[gflat]);
  }
}

// ---------------- K1: projections v2 (128 co x 128 n, 3 chunk-sets) ---------
#define PRJ_STAGE 18432
#define PRJ_SMEM (2 * PRJ_STAGE * 2)  // 73728 B; conv_s [128][132] fp32 aliases

__device__ __forceinline__ const __nv_bfloat16* prj_wrow(int cs, int row) {
  if (cs == 0)
    return (row < 64) ? d_wf + (size_t)row * CC : d_wg + (size_t)(row - 64) * CC;
  return d_wh + (size_t)((cs - 1) * 128 + row) * CC;
}

__global__ void __launch_bounds__(256, 2) proj_mma() {
  extern __shared__ __align__(16) char smc[];
  const int b = blockIdx.z, cs = blockIdx.y, n0 = blockIdx.x * 128;
  const int tid = threadIdx.x, lane = tid & 31, wid = tid >> 5;
  const int warp_m = wid >> 1;  // 0..3 : 32 co rows
  const int warp_n = wid & 1;   // 0..1 : 64 n cols

  float acc[2][8][4];
#pragma unroll
  for (int m = 0; m < 2; m++)
#pragma unroll
    for (int i = 0; i < 8; i++)
#pragma unroll
      for (int j = 0; j < 4; j++) acc[m][i][j] = 0.f;

  const int a_r15 = lane & 15;
  const int a_col = (lane >> 4) << 3;
  const int g8 = lane >> 3, r8 = lane & 7;
  const int b_row = ((g8 >> 1) << 3) + r8;
  const int b_colk = (g8 & 1) << 3;

  const __nv_bfloat16* xtb = d_xt + ((size_t)b * NN + n0) * CC;

  {
    __nv_bfloat16* ws = (__nv_bfloat16*)smc;
    __nv_bfloat16* xs = ws + 128 * 72;
#pragma unroll
    for (int i = 0; i < 4; i++) {
      int flat = tid + i * 256;
      int row = flat >> 3, seg = flat & 7;
      cp16(&ws[row * 72 + seg * 8], prj_wrow(cs, row) + seg * 8);
      cp16(&xs[row * 72 + seg * 8], &xtb[(size_t)row * CC + seg * 8]);
    }
    cp_commit();
  }

  for (int c = 0; c < 8; c++) {
    cp_wait<0>();
    __syncthreads();
    if (c < 7) {
      int kc = (c + 1) * 64;
      __nv_bfloat16* ws = (__nv_bfloat16*)smc + ((c + 1) & 1) * PRJ_STAGE;
      __nv_bfloat16* xs = ws + 128 * 72;
#pragma unroll
      for (int i = 0; i < 4; i++) {
        int flat = tid + i * 256;
        int row = flat >> 3, seg = flat & 7;
        cp16(&ws[row * 72 + seg * 8], prj_wrow(cs, row) + kc + seg * 8);
        cp16(&xs[row * 72 + seg * 8], &xtb[(size_t)row * CC + kc + seg * 8]);
      }
      cp_commit();
    }
    __nv_bfloat16* ws = (__nv_bfloat16*)smc + (c & 1) * PRJ_STAGE;
    __nv_bfloat16* xs = ws + 128 * 72;
#pragma unroll
    for (int ks = 0; ks < 64; ks += 16) {
      uint32_t a[2][4];
#pragma unroll
      for (int mf = 0; mf < 2; mf++)
        ldsm_x4(a[mf][0], a[mf][1], a[mf][2], a[mf][3],
                smem_u32(&ws[(warp_m * 32 + mf * 16 + a_r15) * 72 + ks + a_col]));
#pragma unroll
      for (int nf2 = 0; nf2 < 4; nf2++) {
        uint32_t b0r, b1r, b2r, b3r;
        ldsm_x4(b0r, b1r, b2r, b3r,
                smem_u32(&xs[(warp_n * 64 + nf2 * 16 + b_row) * 72 + ks + b_colk]));
#pragma unroll
        for (int mf = 0; mf < 2; mf++) {
          mma16816(acc[mf][nf2 * 2], a[mf][0], a[mf][1], a[mf][2], a[mf][3],
                   b0r, b1r);
          mma16816(acc[mf][nf2 * 2 + 1], a[mf][0], a[mf][1], a[mf][2],
                   a[mf][3], b2r, b3r);
        }
      }
    }
  }
  __syncthreads();  // conv_s aliases stage buffers

  float* conv_s = (float*)smc;  // [128][132]
#pragma unroll
  for (int mf = 0; mf < 2; mf++) {
    int row0 = warp_m * 32 + mf * 16 + (lane >> 2);
#pragma unroll
    for (int nf = 0; nf < 8; nf++) {
      int col = warp_n * 64 + nf * 8 + (lane & 3) * 2;
      *(float2*)&conv_s[row0 * 132 + col] =
          make_float2(acc[mf][nf][0], acc[mf][nf][1]);
      *(float2*)&conv_s[(row0 + 8) * 132 + col] =
          make_float2(acc[mf][nf][2], acc[mf][nf][3]);
    }
  }
  __syncthreads();

  if (cs == 0) {
#pragma unroll
    for (int i = 0; i < 4; i++) {
      int flat = tid + i * 256;
      int n = flat >> 3, cseg = flat & 7;
      __nv_bfloat16 tmp[8];
#pragma unroll
      for (int c = 0; c < 8; c++)
        tmp[c] = __float2bfloat16_rn(conv_s[(cseg * 8 + c) * 132 + n]);
      *(uint4*)&d_f[((size_t)b * NN + n0 + n) * CI_ + cseg * 8] = *(uint4*)tmp;
    }
    {
      int pj = tid >> 3, cseg = tid & 7;
      __nv_bfloat16 tmp[8];
#pragma unroll
      for (int c = 0; c < 8; c++) {
        const float* r0 = &conv_s[(64 + cseg * 8 + c) * 132];
        float m = fmaxf(fmaxf(r0[2 * pj], r0[2 * pj + 1]),
                        fmaxf(r0[64 + 2 * pj], r0[65 + 2 * pj]));
        tmp[c] = __float2bfloat16_rn(m);
      }
      *(uint4*)&d_g[((size_t)b * PP + blockIdx.x * 32 + pj) * CI_ + cseg * 8] =
          *(uint4*)tmp;
    }
  } else {
#pragma unroll
    for (int i = 0; i < 2; i++) {
      int flat = tid + i * 256;
      int ch = flat >> 2, pseg = flat & 3;
      const float* r0 = &conv_s[ch * 132];
      __nv_bfloat16 tmp[8];
#pragma unroll
      for (int j = 0; j < 8; j++) {
        int pj = pseg * 8 + j;
        float m = fmaxf(fmaxf(r0[2 * pj], r0[2 * pj + 1]),
                        fmaxf(r0[64 + 2 * pj], r0[65 + 2 * pj]));
        tmp[j] = __float2bfloat16_rn(m);
      }
      *(uint4*)&d_hT[((size_t)b * CH_ + (cs - 1) * 128 + ch) * PP +
                     blockIdx.x * 32 + pseg * 8] = *(uint4*)tmp;
    }
  }
}

// ---------------- K2: attention (bf16 MMA; prefetch at chunk top) ----------
#define AT_FS 0
#define AT_GS 4608
#define AT_HS 13824
#define AT_PS 50688
#define AT_END 55296
#define ATTN_SMEM (AT_END * 2 + 64 * 4)  // 110848 B -> 2 CTAs/SM

__global__ void __launch_bounds__(256, 2) attn_mma() {
  extern __shared__ __align__(16) char smc[];
  __nv_bfloat16* fs = (__nv_bfloat16*)smc + AT_FS;
  __nv_bfloat16* ps = (__nv_bfloat16*)smc + AT_PS;
  float* rowsum = (float*)(smc + AT_END * 2);

  const int b = blockIdx.y, n0 = blockIdx.x * 64;
  const int tid = threadIdx.x, lane = tid & 31, wid = tid >> 5;
  const int wm = wid >> 2;  // 0..1 : 32 query rows
  const int wn = wid & 3;   // 0..3 : 16 p (scores) / 64 ch (value)

  if (tid < 64) rowsum[tid] = 0.f;

  const __nv_bfloat16* fb = d_f + ((size_t)b * NN + n0) * CI_;
  const __nv_bfloat16* gb = d_g + (size_t)b * PP * CI_;
  const __nv_bfloat16* hb = d_hT + (size_t)b * CH_ * PP;
  const int ld_row = tid >> 3, ld_seg = tid & 7;

  {
#pragma unroll
    for (int i = 0; i < 2; i++) {
      int row = ld_row + i * 32;
      cp16(&fs[row * 72 + ld_seg * 8], &fb[(size_t)row * CI_ + ld_seg * 8]);
    }
    __nv_bfloat16* gs = (__nv_bfloat16*)smc + AT_GS;
    __nv_bfloat16* hs = (__nv_bfloat16*)smc + AT_HS;
#pragma unroll
    for (int i = 0; i < 2; i++) {
      int row = ld_row + i * 32;
      cp16(&gs[row * 72 + ld_seg * 8], &gb[(size_t)row * CI_ + ld_seg * 8]);
    }
#pragma unroll
    for (int i = 0; i < 8; i++) {
      int row = ld_row + i * 32;
      cp16(&hs[row * 72 + ld_seg * 8], &hb[(size_t)row * PP + ld_seg * 8]);
    }
    cp_commit();
  }

  const int a_col = (lane >> 4) << 3;
  const int a_r15 = lane & 15;
  const int g8 = lane >> 3, r8 = lane & 7;
  const int b_row = ((g8 >> 1) << 3) + r8;
  const int b_colk = (g8 & 1) << 3;

  float vacc[2][8][4];
#pragma unroll
  for (int m = 0; m < 2; m++)
#pragma unroll
    for (int c = 0; c < 8; c++)
#pragma unroll
      for (int j = 0; j < 4; j++) vacc[m][c][j] = 0.f;
  float rs[2][2] = {{0.f, 0.f}, {0.f, 0.f}};

  for (int c = 0; c < 16; c++) {
    cp_wait<0>();
    __syncthreads();  // chunk c ready; all warps past value(c-1)

    if (c < 15) {  // prefetch c+1 at chunk top (buffer (c+1)&1 is dead)
      int pc = (c + 1) * 64;
      __nv_bfloat16* gs2 = (__nv_bfloat16*)smc + AT_GS + ((c + 1) & 1) * 4608;
      __nv_bfloat16* hs2 = (__nv_bfloat16*)smc + AT_HS + ((c + 1) & 1) * 18432;
#pragma unroll
      for (int i = 0; i < 2; i++) {
        int row = ld_row + i * 32;
        cp16(&gs2[row * 72 + ld_seg * 8],
             &gb[(size_t)(pc + row) * CI_ + ld_seg * 8]);
      }
#pragma unroll
      for (int i = 0; i < 8; i++) {
        int row = ld_row + i * 32;
        cp16(&hs2[row * 72 + ld_seg * 8],
             &hb[(size_t)row * PP + pc + ld_seg * 8]);
      }
      cp_commit();
    }

    __nv_bfloat16* gs = (__nv_bfloat16*)smc + AT_GS + (c & 1) * 4608;
    __nv_bfloat16* hs = (__nv_bfloat16*)smc + AT_HS + (c & 1) * 18432;

    // ---- scores: [64 n][64 p], K=64 (log2-domain) ----
    float sacc[2][2][4];
#pragma unroll
    for (int m = 0; m < 2; m++)
#pragma unroll
      for (int p = 0; p < 2; p++)
#pragma unroll
        for (int j = 0; j < 4; j++) sacc[m][p][j] = 0.f;
#pragma unroll
    for (int ks = 0; ks < 64; ks += 16) {
      uint32_t a[2][4];
#pragma unroll
      for (int mf = 0; mf < 2; mf++)
        ldsm_x4(a[mf][0], a[mf][1], a[mf][2], a[mf][3],
                smem_u32(&fs[(wm * 32 + mf * 16 + a_r15) * 72 + ks + a_col]));
      uint32_t b0r, b1r, b2r, b3r;
      ldsm_x4(b0r, b1r, b2r, b3r,
              smem_u32(&gs[(wn * 16 + b_row) * 72 + ks + b_colk]));
#pragma unroll
      for (int mf = 0; mf < 2; mf++) {
        mma16816(sacc[mf][0], a[mf][0], a[mf][1], a[mf][2], a[mf][3], b0r, b1r);
        mma16816(sacc[mf][1], a[mf][0], a[mf][1], a[mf][2], a[mf][3], b2r, b3r);
      }
    }
    // Schraudolph 2^s, probs -> smem via PRMT
#pragma unroll
    for (int mf = 0; mf < 2; mf++) {
      int row = wm * 32 + mf * 16 + (lane >> 2);
#pragma unroll
      for (int pf = 0; pf < 2; pf++) {
        uint32_t u0 = exp2_bits(sacc[mf][pf][0]);
        uint32_t u1 = exp2_bits(sacc[mf][pf][1]);
        uint32_t u2 = exp2_bits(sacc[mf][pf][2]);
        uint32_t u3 = exp2_bits(sacc[mf][pf][3]);
        rs[mf][0] += __uint_as_float(u0) + __uint_as_float(u1);
        rs[mf][1] += __uint_as_float(u2) + __uint_as_float(u3);
        int col = wn * 16 + pf * 8 + (lane & 3) * 2;
        *(uint32_t*)&ps[row * 72 + col] = __byte_perm(u0, u1, 0x7632);
        *(uint32_t*)&ps[(row + 8) * 72 + col] = __byte_perm(u2, u3, 0x7632);
      }
    }
    NAMED_BAR(1 + wm, 128);  // ps rows [wm*32,+32) complete within wm-group

    // ---- value: [64 n][256 ch], K=64 ----
#pragma unroll
    for (int ks = 0; ks < 64; ks += 16) {
      uint32_t a[2][4];
#pragma unroll
      for (int mf = 0; mf < 2; mf++)
        ldsm_x4(a[mf][0], a[mf][1], a[mf][2], a[mf][3],
                smem_u32(&ps[(wm * 32 + mf * 16 + a_r15) * 72 + ks + a_col]));
#pragma unroll
      for (int cf2 = 0; cf2 < 4; cf2++) {
        int cb = wn * 64 + cf2 * 16;
        uint32_t b0r, b1r, b2r, b3r;
        ldsm_x4(b0r, b1r, b2r, b3r,
                smem_u32(&hs[(cb + b_row) * 72 + ks + b_colk]));
#pragma unroll
        for (int mf = 0; mf < 2; mf++) {
          mma16816(vacc[mf][cf2 * 2], a[mf][0], a[mf][1], a[mf][2], a[mf][3],
                   b0r, b1r);
          mma16816(vacc[mf][cf2 * 2 + 1], a[mf][0], a[mf][1], a[mf][2],
                   a[mf][3], b2r, b3r);
        }
      }
    }
  }

  // rowsum: one reduce + atomic at the end
#pragma unroll
  for (int mf = 0; mf < 2; mf++)
#pragma unroll
    for (int h = 0; h < 2; h++) {
      float v = rs[mf][h];
      v += __shfl_xor_sync(0xffffffffu, v, 1);
      v += __shfl_xor_sync(0xffffffffu, v, 2);
      if ((lane & 3) == 0)
        atomicAdd(&rowsum[wm * 32 + mf * 16 + (lane >> 2) + h * 8], v);
    }
  __syncthreads();

  // normalize + write v [B][N][CH] bf16
#pragma unroll
  for (int mf = 0; mf < 2; mf++) {
    int r = wm * 32 + mf * 16 + (lane >> 2);
    float inv0 = 1.f / rowsum[r];
    float inv8 = 1.f / rowsum[r + 8];
    size_t base0 = ((size_t)b * NN + n0 + r) * CH_;
    size_t base8 = ((size_t)b * NN + n0 + r + 8) * CH_;
#pragma unroll
    for (int cf = 0; cf < 8; cf++) {
      int ch = wn * 64 + cf * 8 + (lane & 3) * 2;
      *(uint32_t*)&d_v[base0 + ch] =
          bf2pack(vacc[mf][cf][0] * inv0, vacc[mf][cf][1] * inv0);
      *(uint32_t*)&d_v[base8 + ch] =
          bf2pack(vacc[mf][cf][2] * inv8, vacc[mf][cf][3] * inv8);
    }
  }
}

// ---------------- K3 v3: out = x + beta*(Wv@v); [128 co][128 n] tiles -------
// v re-read factor 4 (was 8): halves redundant DRAM traffic.
#define OUT_STAGE 18432
#define OUT_SMEM (2 * OUT_STAGE * 2)  // 73728 B -> 2 CTAs/SM

__global__ void __launch_bounds__(256, 2) outconv_mma(
    const float* __restrict__ x, const float* __restrict__ beta,
    float* __restrict__ out) {
  extern __shared__ __align__(16) char smc[];
  const int b = blockIdx.z, co0 = blockIdx.y * 128, n0 = blockIdx.x * 128;
  const int tid = threadIdx.x, lane = tid & 31, wid = tid >> 5;
  const int warp_m = wid >> 1;  // 0..3 : 32 co rows
  const int warp_n = wid & 1;   // 0..1 : 64 n cols

  float acc[2][8][4];
#pragma unroll
  for (int m = 0; m < 2; m++)
#pragma unroll
    for (int i = 0; i < 8; i++)
#pragma unroll
      for (int j = 0; j < 4; j++) acc[m][i][j] = 0.f;

  const int a_r15 = lane & 15;
  const int a_col = (lane >> 4) << 3;
  const int g8 = lane >> 3, r8 = lane & 7;
  const int b_row = ((g8 >> 1) << 3) + r8;
  const int b_colk = (g8 & 1) << 3;

  const __nv_bfloat16* vb = d_v + ((size_t)b * NN + n0) * CH_;
  const __nv_bfloat16* Wb = d_wv + (size_t)co0 * CH_;

  {
    __nv_bfloat16* ws = (__nv_bfloat16*)smc;
    __nv_bfloat16* vs = ws + 128 * 72;
#pragma unroll
    for (int i = 0; i < 4; i++) {
      int flat = tid + i * 256;
      int row = flat >> 3, seg = flat & 7;
      cp16(&ws[row * 72 + seg * 8], &Wb[(size_t)row * CH_ + seg * 8]);
      cp16(&vs[row * 72 + seg * 8], &vb[(size_t)row * CH_ + seg * 8]);
    }
    cp_commit();
  }

  for (int c = 0; c < 4; c++) {
    cp_wait<0>();
    __syncthreads();
    if (c < 3) {
      int kc = (c + 1) * 64;
      __nv_bfloat16* ws = (__nv_bfloat16*)smc + ((c + 1) & 1) * OUT_STAGE;
      __nv_bfloat16* vs = ws + 128 * 72;
#pragma unroll
      for (int i = 0; i < 4; i++) {
        int flat = tid + i * 256;
        int row = flat >> 3, seg = flat & 7;
        cp16(&ws[row * 72 + seg * 8], &Wb[(size_t)row * CH_ + kc + seg * 8]);
        cp16(&vs[row * 72 + seg * 8], &vb[(size_t)row * CH_ + kc + seg * 8]);
      }
      cp_commit();
    }
    __nv_bfloat16* ws = (__nv_bfloat16*)smc + (c & 1) * OUT_STAGE;
    __nv_bfloat16* vs = ws + 128 * 72;
#pragma unroll
    for (int ks = 0; ks < 64; ks += 16) {
      uint32_t a[2][4];
#pragma unroll
      for (int mf = 0; mf < 2; mf++)
        ldsm_x4(a[mf][0], a[mf][1], a[mf][2], a[mf][3],
                smem_u32(&ws[(warp_m * 32 + mf * 16 + a_r15) * 72 + ks + a_col]));
#pragma unroll
      for (int nf2 = 0; nf2 < 4; nf2++) {
        uint32_t b0r, b1r, b2r, b3r;
        ldsm_x4(b0r, b1r, b2r, b3r,
                smem_u32(&vs[(warp_n * 64 + nf2 * 16 + b_row) * 72 + ks + b_colk]));
#pragma unroll
        for (int mf = 0; mf < 2; mf++) {
          mma16816(acc[mf][nf2 * 2], a[mf][0], a[mf][1], a[mf][2], a[mf][3],
                   b0r, b1r);
          mma16816(acc[mf][nf2 * 2 + 1], a[mf][0], a[mf][1], a[mf][2],
                   a[mf][3], b2r, b3r);
        }
      }
    }
  }

  const float bv = beta[0];
#pragma unroll
  for (int mf = 0; mf < 2; mf++) {
    int row = co0 + warp_m * 32 + mf * 16 + (lane >> 2);
#pragma unroll
    for (int nf = 0; nf < 8; nf++) {
      int col = warp_n * 64 + nf * 8 + (lane & 3) * 2;
      size_t idx0 = ((size_t)b * CC + row) * NN + n0 + col;
      size_t idx8 = ((size_t)b * CC + row + 8) * NN + n0 + col;
      float2 xv0 = *(const float2*)&x[idx0];
      float2 xv8 = *(const float2*)&x[idx8];
      *(float2*)&out[idx0] =
          make_float2(xv0.x + bv * acc[mf][nf][0], xv0.y + bv * acc[mf][nf][1]);
      *(float2*)&out[idx8] =
          make_float2(xv8.x + bv * acc[mf][nf][2], xv8.y + bv * acc[mf][nf][3]);
    }
  }
}

// ---------------------------------------------------------------------------
extern "C" void kernel_launch(void* const* d_in, const int* in_sizes, int n_in,
                              void* d_out, int out_size) {
  (void)in_sizes; (void)n_in; (void)out_size;
  const float* x = (const float*)d_in[0];
  const float* Wf = (const float*)d_in[1];
  const float* Wg = (const float*)d_in[2];
  const float* Wh = (const float*)d_in[3];
  const float* Wv = (const float*)d_in[4];
  const float* beta = (const float*)d_in[5];
  float* out = (float*)d_out;

  convert_x<<<dim3(64, 8, BB), 256>>>(x, Wf, Wg, Wh, Wv);

  cudaFuncSetAttribute(proj_mma, cudaFuncAttributeMaxDynamicSharedMemorySize,
                       PRJ_SMEM);
  proj_mma<<<dim3(32, 3, BB), 256, PRJ_SMEM>>>();

  cudaFuncSetAttribute(attn_mma, cudaFuncAttributeMaxDynamicSharedMemorySize,
                       ATTN_SMEM);
  attn_mma<<<dim3(64, BB), 256, ATTN_SMEM>>>();

  cudaFuncSetAttribute(outconv_mma, cudaFuncAttributeMaxDynamicSharedMemorySize,
                       OUT_SMEM);
  outconv_mma<<<dim3(32, 4, BB), 256, OUT_SMEM>>>(x, beta, out);
}